// round 7
// baseline (speedup 1.0000x reference)
#include <cuda_runtime.h>
#include <cuda_fp16.h>
#include <cstdint>

#define NATOMS 50000
#define NEDGES 800000
#define CHUNK  16
#define MAXCHUNKS (NATOMS + NEDGES / CHUNK)   // 100000 upper bound

// scratch
__device__ __half2 g_xm[NATOMS * 192];   // per atom: 96 half2 x, then 96 half2 mu
__device__ int     g_cnt[NATOMS];
__device__ int     g_off[NATOMS];
__device__ int     g_cur[NATOMS];
__device__ int2    g_pe[NEDGES];         // (e, j) sorted by idx_i
__device__ float4  g_sdir[NEDGES];       // dir sorted by idx_i (w unused)
__device__ int2    g_chunks[MAXCHUNKS];  // (beg, (cnt<<16)|i)
__device__ int     g_nchunks;

// ---- packed f32x2 helpers -------------------------------------------------
#define PK2(d, lo, hi) \
    asm("mov.b64 %0, {%1, %2};" : "=l"(d) : "r"(__float_as_uint(lo)), "r"(__float_as_uint(hi)))
#define UPK2(lo, hi, d) do { unsigned _ulo, _uhi; \
    asm("mov.b64 {%0, %1}, %2;" : "=r"(_ulo), "=r"(_uhi) : "l"(d)); \
    lo = __uint_as_float(_ulo); hi = __uint_as_float(_uhi); } while (0)
#define FMA2(acc, a, b) \
    asm("fma.rn.f32x2 %0, %1, %2, %0;" : "+l"(acc) : "l"(a), "l"(b))

#define HSTRIDE 68

// ---------------------------------------------------------------------------
// Kernel A: per-atom MLP -> fp16 x into g_xm[:,0:96]
// ---------------------------------------------------------------------------
__global__ __launch_bounds__(256) void painn_mlp_kernel(
    const float* __restrict__ q,
    const float* __restrict__ W1, const float* __restrict__ b1,
    const float* __restrict__ W2, const float* __restrict__ b2)
{
    __shared__ float sH[128 * HSTRIDE];
    __shared__ float sB2[192];

    const int t = threadIdx.x;
    const int atom0 = blockIdx.x * 128;
    const int tx = t & 15;
    const int ty = t >> 4;

    for (int k = t; k < 128 * 16; k += 256) {
        int a = k >> 4, c4 = k & 15;
        int ga = atom0 + a;
        float4 v = (ga < NATOMS) ? __ldg((const float4*)q + (size_t)ga * 16 + c4)
                                 : make_float4(0.f, 0.f, 0.f, 0.f);
        *(float4*)&sH[a * HSTRIDE + c4 * 4] = v;
    }
    if (t < 192) sB2[t] = b2[t];
    __syncthreads();

    unsigned long long acc1[8][2];
#pragma unroll
    for (int r = 0; r < 8; r++) { acc1[r][0] = 0ull; acc1[r][1] = 0ull; }

    const float4* W1v = (const float4*)W1;
#pragma unroll 4
    for (int k = 0; k < 64; k++) {
        float4 w = __ldg(&W1v[k * 16 + tx]);
        unsigned long long wp0, wp1;
        PK2(wp0, w.x, w.y);
        PK2(wp1, w.z, w.w);
#pragma unroll
        for (int r = 0; r < 8; r++) {
            float h = sH[(ty * 8 + r) * HSTRIDE + k];
            unsigned long long hp;
            PK2(hp, h, h);
            FMA2(acc1[r][0], hp, wp0);
            FMA2(acc1[r][1], hp, wp1);
        }
    }
    __syncthreads();

    {
        float b0 = __ldg(&b1[tx * 4 + 0]);
        float bb1 = __ldg(&b1[tx * 4 + 1]);
        float b2v = __ldg(&b1[tx * 4 + 2]);
        float b3 = __ldg(&b1[tx * 4 + 3]);
#pragma unroll
        for (int r = 0; r < 8; r++) {
            float v0, v1, v2, v3;
            UPK2(v0, v1, acc1[r][0]);
            UPK2(v2, v3, acc1[r][1]);
            v0 += b0; v1 += bb1; v2 += b2v; v3 += b3;
            v0 = v0 / (1.0f + __expf(-v0));
            v1 = v1 / (1.0f + __expf(-v1));
            v2 = v2 / (1.0f + __expf(-v2));
            v3 = v3 / (1.0f + __expf(-v3));
            float* row = &sH[(ty * 8 + r) * HSTRIDE + tx * 4];
            row[0] = v0; row[1] = v1; row[2] = v2; row[3] = v3;
        }
    }
    __syncthreads();

    unsigned long long a2[8][6];
#pragma unroll
    for (int r = 0; r < 8; r++)
#pragma unroll
        for (int c = 0; c < 6; c++) a2[r][c] = 0ull;

    const float4* W2v = (const float4*)W2;
    const int oc4 = tx * 3;
#pragma unroll 2
    for (int k = 0; k < 64; k++) {
        float4 wa = __ldg(&W2v[k * 48 + oc4 + 0]);
        float4 wb = __ldg(&W2v[k * 48 + oc4 + 1]);
        float4 wc = __ldg(&W2v[k * 48 + oc4 + 2]);
        unsigned long long w0, w1, w2, w3, w4, w5;
        PK2(w0, wa.x, wa.y); PK2(w1, wa.z, wa.w);
        PK2(w2, wb.x, wb.y); PK2(w3, wb.z, wb.w);
        PK2(w4, wc.x, wc.y); PK2(w5, wc.z, wc.w);
#pragma unroll
        for (int r = 0; r < 8; r++) {
            float h = sH[(ty * 8 + r) * HSTRIDE + k];
            unsigned long long hp;
            PK2(hp, h, h);
            FMA2(a2[r][0], hp, w0);
            FMA2(a2[r][1], hp, w1);
            FMA2(a2[r][2], hp, w2);
            FMA2(a2[r][3], hp, w3);
            FMA2(a2[r][4], hp, w4);
            FMA2(a2[r][5], hp, w5);
        }
    }

    const int ocol = tx * 12;
#pragma unroll
    for (int r = 0; r < 8; r++) {
        int atom = atom0 + ty * 8 + r;
        if (atom < NATOMS) {
            float v[12];
#pragma unroll
            for (int c = 0; c < 6; c++) UPK2(v[2 * c], v[2 * c + 1], a2[r][c]);
            __half2* dst = &g_xm[(size_t)atom * 192 + tx * 6];
#pragma unroll
            for (int c = 0; c < 6; c++) {
                dst[c] = __floats2half2_rn(v[2 * c] + sB2[ocol + 2 * c],
                                           v[2 * c + 1] + sB2[ocol + 2 * c + 1]);
            }
        }
    }
}

// ---------------------------------------------------------------------------
// Fused: out = concat(q, mu)  AND  g_xm[:,96:192] = fp16(mu)
// index space: float2 elements of out (NATOMS*128)
// ---------------------------------------------------------------------------
__global__ __launch_bounds__(256) void init_fuse_kernel(
    const float* __restrict__ q, const float* __restrict__ mu,
    float* __restrict__ out)
{
    const int NQ2 = NATOMS * 32;        // float2 count of q part
    const int NT2 = NATOMS * 128;       // total float2
    int i = blockIdx.x * blockDim.x + threadIdx.x;
    if (i < NQ2) {
        ((float2*)out)[i] = ((const float2*)q)[i];
    } else if (i < NT2) {
        int m = i - NQ2;                // float2 index into mu
        float2 v = __ldg((const float2*)mu + m);
        ((float2*)out)[i] = v;
        g_xm[(size_t)(m / 96) * 192 + 96 + (m % 96)] = __floats2half2_rn(v.x, v.y);
    }
}

// ---------------------------------------------------------------------------
// Sort-by-i prep
// ---------------------------------------------------------------------------
__global__ __launch_bounds__(256) void zero_cnt_kernel() {
    int i = blockIdx.x * blockDim.x + threadIdx.x;
    if (i < NATOMS) { g_cnt[i] = 0; g_cur[i] = 0; }
    if (i == 0) g_nchunks = 0;
}

__global__ __launch_bounds__(256) void hist_kernel(const int* __restrict__ idx_i) {
    int e = blockIdx.x * blockDim.x + threadIdx.x;
    if (e < NEDGES) atomicAdd(&g_cnt[__ldg(&idx_i[e])], 1);
}

__global__ __launch_bounds__(1024) void scan_kernel() {
    __shared__ int s[1024];
    const int T = 1024;
    const int t = threadIdx.x;
    const int CH = (NATOMS + T - 1) / T;
    const int base = t * CH;

    int sum = 0;
    for (int k = 0; k < CH; k++) {
        int idx = base + k;
        if (idx < NATOMS) sum += g_cnt[idx];
    }
    s[t] = sum;
    __syncthreads();
    for (int off = 1; off < T; off <<= 1) {
        int add = (t >= off) ? s[t - off] : 0;
        __syncthreads();
        s[t] += add;
        __syncthreads();
    }
    int run = s[t] - sum;
    for (int k = 0; k < CH; k++) {
        int idx = base + k;
        if (idx < NATOMS) { g_off[idx] = run; run += g_cnt[idx]; }
    }
}

__global__ __launch_bounds__(256) void scatter_kernel(
    const int* __restrict__ idx_i, const int* __restrict__ idx_j,
    const float* __restrict__ dir_ij)
{
    int e = blockIdx.x * blockDim.x + threadIdx.x;
    if (e < NEDGES) {
        int i = __ldg(&idx_i[e]);
        int j = __ldg(&idx_j[e]);
        int pos = g_off[i] + atomicAdd(&g_cur[i], 1);
        g_pe[pos] = make_int2(e, j);
        float4 d;
        d.x = __ldg(&dir_ij[(size_t)e * 3 + 0]);
        d.y = __ldg(&dir_ij[(size_t)e * 3 + 1]);
        d.z = __ldg(&dir_ij[(size_t)e * 3 + 2]);
        d.w = 0.f;
        g_sdir[pos] = d;
    }
}

// one thread per atom: emit ceil(cnt/CHUNK) chunks (order irrelevant)
__global__ __launch_bounds__(256) void chunk_kernel() {
    int i = blockIdx.x * blockDim.x + threadIdx.x;
    if (i >= NATOMS) return;
    int cnt = g_cnt[i];
    int off = g_off[i];
    while (cnt > 0) {
        int c = cnt < CHUNK ? cnt : CHUNK;
        int pos = atomicAdd(&g_nchunks, 1);
        g_chunks[pos] = make_int2(off, (c << 16) | i);
        off += c;
        cnt -= c;
    }
}

// ---------------------------------------------------------------------------
// Kernel C: one warp per chunk (single atom, <=16 edges), branch-free loop,
// single red2 flush at end. Lane owns features {2l, 2l+1}.
// ---------------------------------------------------------------------------
__device__ __forceinline__ void red2(float* p, float a, float b) {
    asm volatile("red.global.add.v2.f32 [%0], {%1, %2};"
                 :: "l"(p), "f"(a), "f"(b) : "memory");
}

__global__ __launch_bounds__(256) void painn_edge_kernel(
    const float* __restrict__ Wij, float* __restrict__ out)
{
    const int warp = (blockIdx.x * blockDim.x + threadIdx.x) >> 5;
    const int lane = threadIdx.x & 31;
    if (warp >= g_nchunks) return;

    const int2 ck = __ldg(&g_chunks[warp]);
    const int beg = ck.x;
    const int cnt = ck.y >> 16;
    const int i   = ck.y & 0xFFFF;
    const int end = beg + cnt;

    float aqx = 0.f, aqy = 0.f;
    float a0x = 0.f, a0y = 0.f;
    float a1x = 0.f, a1y = 0.f;
    float a2x = 0.f, a2y = 0.f;

#pragma unroll 4
    for (int p = beg; p < end; p++) {
        const int2 ej = __ldg(&g_pe[p]);
        const float4 d = __ldg(&g_sdir[p]);
        const int e = ej.x, j = ej.y;

        const float2* W2p = (const float2*)(Wij + (size_t)e * 192);
        const __half2* T = g_xm + (size_t)j * 192;

        const float2 w0 = __ldg(&W2p[lane]);
        const float2 w1 = __ldg(&W2p[32 + lane]);
        const float2 w2 = __ldg(&W2p[64 + lane]);
        const float2 x0 = __half22float2(__ldg(&T[lane]));
        const float2 x1 = __half22float2(__ldg(&T[32 + lane]));
        const float2 x2 = __half22float2(__ldg(&T[64 + lane]));
        const float2 m0 = __half22float2(__ldg(&T[96 + lane]));
        const float2 m1 = __half22float2(__ldg(&T[128 + lane]));
        const float2 m2 = __half22float2(__ldg(&T[160 + lane]));

        aqx = fmaf(w0.x, x0.x, aqx);
        aqy = fmaf(w0.y, x0.y, aqy);

        const float mRx = w1.x * x1.x, mRy = w1.y * x1.y;
        const float mMx = w2.x * x2.x, mMy = w2.y * x2.y;

        a0x = fmaf(mRx, d.x, fmaf(mMx, m0.x, a0x));
        a0y = fmaf(mRy, d.x, fmaf(mMy, m0.y, a0y));
        a1x = fmaf(mRx, d.y, fmaf(mMx, m1.x, a1x));
        a1y = fmaf(mRy, d.y, fmaf(mMy, m1.y, a1y));
        a2x = fmaf(mRx, d.z, fmaf(mMx, m2.x, a2x));
        a2y = fmaf(mRy, d.z, fmaf(mMy, m2.y, a2y));
    }

    red2(out + (size_t)i * 64 + lane * 2, aqx, aqy);
    float* om = out + (size_t)NATOMS * 64 + (size_t)i * 192 + lane * 2;
    red2(om,       a0x, a0y);
    red2(om + 64,  a1x, a1y);
    red2(om + 128, a2x, a2y);
}

// ---------------------------------------------------------------------------
// launch
// ---------------------------------------------------------------------------
extern "C" void kernel_launch(void* const* d_in, const int* in_sizes, int n_in,
                              void* d_out, int out_size)
{
    int iq = -1, imu = -1, iW = -1, idir = -1, ii = -1, ij = -1;
    int iW1 = -1, ib1 = -1, iW2 = -1, ib2 = -1;
    for (int k = 0; k < n_in; k++) {
        long s = in_sizes[k];
        if      (s == (long)NATOMS * 64)   iq  = k;
        else if (s == (long)NATOMS * 192)  imu = k;
        else if (s == (long)NEDGES * 192)  iW  = k;
        else if (s == (long)NEDGES * 3)    idir = k;
        else if (s == (long)NEDGES)        { if (ii < 0) ii = k; else ij = k; }
        else if (s == 64 * 64)             iW1 = k;
        else if (s == 64)                  ib1 = k;
        else if (s == 64 * 192)            iW2 = k;
        else if (s == 192)                 ib2 = k;
    }

    const float* q   = (const float*)d_in[iq];
    const float* mu  = (const float*)d_in[imu];
    const float* Wij = (const float*)d_in[iW];
    const float* dir = (const float*)d_in[idir];
    const int*  idxi = (const int*)d_in[ii];
    const int*  idxj = (const int*)d_in[ij];
    const float* W1  = (const float*)d_in[iW1];
    const float* b1  = (const float*)d_in[ib1];
    const float* W2  = (const float*)d_in[iW2];
    const float* b2  = (const float*)d_in[ib2];
    float* out = (float*)d_out;

    // prep: sort edges by idx_i, build chunks
    zero_cnt_kernel<<<(NATOMS + 255) / 256, 256>>>();
    hist_kernel<<<(NEDGES + 255) / 256, 256>>>(idxi);
    scan_kernel<<<1, 1024>>>();
    scatter_kernel<<<(NEDGES + 255) / 256, 256>>>(idxi, idxj, dir);
    chunk_kernel<<<(NATOMS + 255) / 256, 256>>>();

    // per-atom MLP -> fp16 x part of g_xm
    painn_mlp_kernel<<<(NATOMS + 127) / 128, 256>>>(q, W1, b1, W2, b2);

    // out = concat(q, mu) + fp16 mu table
    {
        const int total2 = NATOMS * 128;
        init_fuse_kernel<<<(total2 + 255) / 256, 256>>>(q, mu, out);
    }

    // edge chunks (one warp each); launch upper bound, early-exit beyond count
    {
        const int warps_per_block = 256 / 32;
        const int blocks = (MAXCHUNKS + warps_per_block - 1) / warps_per_block;
        painn_edge_kernel<<<blocks, 256>>>(Wij, out);
    }
}

// round 8
// speedup vs baseline: 1.0277x; 1.0277x over previous
#include <cuda_runtime.h>
#include <cuda_fp16.h>
#include <cstdint>

#define NATOMS 50000
#define NEDGES 800000
#define CHUNK  32
#define MAXCHUNKS (NATOMS + NEDGES / CHUNK)   // 75000 upper bound

// scratch
__device__ __half2 g_xm[NATOMS * 192];   // per atom: 96 half2 x, then 96 half2 mu
__device__ int     g_cnt[NATOMS];
__device__ int     g_off[NATOMS];
__device__ int     g_cur[NATOMS];
__device__ int2    g_pe[NEDGES];         // (e, j) sorted by idx_i
__device__ float4  g_sdir[NEDGES];       // dir sorted by idx_i (w unused)
__device__ int2    g_chunks[MAXCHUNKS];  // (beg, (cnt<<16)|i)
__device__ int     g_nchunks;

// ---- packed f32x2 helpers -------------------------------------------------
#define PK2(d, lo, hi) \
    asm("mov.b64 %0, {%1, %2};" : "=l"(d) : "r"(__float_as_uint(lo)), "r"(__float_as_uint(hi)))
#define UPK2(lo, hi, d) do { unsigned _ulo, _uhi; \
    asm("mov.b64 {%0, %1}, %2;" : "=r"(_ulo), "=r"(_uhi) : "l"(d)); \
    lo = __uint_as_float(_ulo); hi = __uint_as_float(_uhi); } while (0)
#define FMA2(acc, a, b) \
    asm("fma.rn.f32x2 %0, %1, %2, %0;" : "+l"(acc) : "l"(a), "l"(b))

#define HSTRIDE 68

// ---------------------------------------------------------------------------
// Kernel A: per-atom MLP -> fp16 x into g_xm[:,0:96]
// ---------------------------------------------------------------------------
__global__ __launch_bounds__(256) void painn_mlp_kernel(
    const float* __restrict__ q,
    const float* __restrict__ W1, const float* __restrict__ b1,
    const float* __restrict__ W2, const float* __restrict__ b2)
{
    __shared__ float sH[128 * HSTRIDE];
    __shared__ float sB2[192];

    const int t = threadIdx.x;
    const int atom0 = blockIdx.x * 128;
    const int tx = t & 15;
    const int ty = t >> 4;

    for (int k = t; k < 128 * 16; k += 256) {
        int a = k >> 4, c4 = k & 15;
        int ga = atom0 + a;
        float4 v = (ga < NATOMS) ? __ldg((const float4*)q + (size_t)ga * 16 + c4)
                                 : make_float4(0.f, 0.f, 0.f, 0.f);
        *(float4*)&sH[a * HSTRIDE + c4 * 4] = v;
    }
    if (t < 192) sB2[t] = b2[t];
    __syncthreads();

    unsigned long long acc1[8][2];
#pragma unroll
    for (int r = 0; r < 8; r++) { acc1[r][0] = 0ull; acc1[r][1] = 0ull; }

    const float4* W1v = (const float4*)W1;
#pragma unroll 4
    for (int k = 0; k < 64; k++) {
        float4 w = __ldg(&W1v[k * 16 + tx]);
        unsigned long long wp0, wp1;
        PK2(wp0, w.x, w.y);
        PK2(wp1, w.z, w.w);
#pragma unroll
        for (int r = 0; r < 8; r++) {
            float h = sH[(ty * 8 + r) * HSTRIDE + k];
            unsigned long long hp;
            PK2(hp, h, h);
            FMA2(acc1[r][0], hp, wp0);
            FMA2(acc1[r][1], hp, wp1);
        }
    }
    __syncthreads();

    {
        float b0 = __ldg(&b1[tx * 4 + 0]);
        float bb1 = __ldg(&b1[tx * 4 + 1]);
        float b2v = __ldg(&b1[tx * 4 + 2]);
        float b3 = __ldg(&b1[tx * 4 + 3]);
#pragma unroll
        for (int r = 0; r < 8; r++) {
            float v0, v1, v2, v3;
            UPK2(v0, v1, acc1[r][0]);
            UPK2(v2, v3, acc1[r][1]);
            v0 += b0; v1 += bb1; v2 += b2v; v3 += b3;
            v0 = v0 / (1.0f + __expf(-v0));
            v1 = v1 / (1.0f + __expf(-v1));
            v2 = v2 / (1.0f + __expf(-v2));
            v3 = v3 / (1.0f + __expf(-v3));
            float* row = &sH[(ty * 8 + r) * HSTRIDE + tx * 4];
            row[0] = v0; row[1] = v1; row[2] = v2; row[3] = v3;
        }
    }
    __syncthreads();

    unsigned long long a2[8][6];
#pragma unroll
    for (int r = 0; r < 8; r++)
#pragma unroll
        for (int c = 0; c < 6; c++) a2[r][c] = 0ull;

    const float4* W2v = (const float4*)W2;
    const int oc4 = tx * 3;
#pragma unroll 2
    for (int k = 0; k < 64; k++) {
        float4 wa = __ldg(&W2v[k * 48 + oc4 + 0]);
        float4 wb = __ldg(&W2v[k * 48 + oc4 + 1]);
        float4 wc = __ldg(&W2v[k * 48 + oc4 + 2]);
        unsigned long long w0, w1, w2, w3, w4, w5;
        PK2(w0, wa.x, wa.y); PK2(w1, wa.z, wa.w);
        PK2(w2, wb.x, wb.y); PK2(w3, wb.z, wb.w);
        PK2(w4, wc.x, wc.y); PK2(w5, wc.z, wc.w);
#pragma unroll
        for (int r = 0; r < 8; r++) {
            float h = sH[(ty * 8 + r) * HSTRIDE + k];
            unsigned long long hp;
            PK2(hp, h, h);
            FMA2(a2[r][0], hp, w0);
            FMA2(a2[r][1], hp, w1);
            FMA2(a2[r][2], hp, w2);
            FMA2(a2[r][3], hp, w3);
            FMA2(a2[r][4], hp, w4);
            FMA2(a2[r][5], hp, w5);
        }
    }

    const int ocol = tx * 12;
#pragma unroll
    for (int r = 0; r < 8; r++) {
        int atom = atom0 + ty * 8 + r;
        if (atom < NATOMS) {
            float v[12];
#pragma unroll
            for (int c = 0; c < 6; c++) UPK2(v[2 * c], v[2 * c + 1], a2[r][c]);
            __half2* dst = &g_xm[(size_t)atom * 192 + tx * 6];
#pragma unroll
            for (int c = 0; c < 6; c++) {
                dst[c] = __floats2half2_rn(v[2 * c] + sB2[ocol + 2 * c],
                                           v[2 * c + 1] + sB2[ocol + 2 * c + 1]);
            }
        }
    }
}

// ---------------------------------------------------------------------------
// Fused: out = concat(q, mu)  AND  g_xm[:,96:192] = fp16(mu)
// ---------------------------------------------------------------------------
__global__ __launch_bounds__(256) void init_fuse_kernel(
    const float* __restrict__ q, const float* __restrict__ mu,
    float* __restrict__ out)
{
    const int NQ2 = NATOMS * 32;
    const int NT2 = NATOMS * 128;
    int i = blockIdx.x * blockDim.x + threadIdx.x;
    if (i < NQ2) {
        ((float2*)out)[i] = ((const float2*)q)[i];
    } else if (i < NT2) {
        int m = i - NQ2;
        float2 v = __ldg((const float2*)mu + m);
        ((float2*)out)[i] = v;
        g_xm[(size_t)(m / 96) * 192 + 96 + (m % 96)] = __floats2half2_rn(v.x, v.y);
    }
}

// ---------------------------------------------------------------------------
// Sort-by-i prep
// ---------------------------------------------------------------------------
__global__ __launch_bounds__(256) void zero_cnt_kernel() {
    int i = blockIdx.x * blockDim.x + threadIdx.x;
    if (i < NATOMS) { g_cnt[i] = 0; g_cur[i] = 0; }
    if (i == 0) g_nchunks = 0;
}

__global__ __launch_bounds__(256) void hist_kernel(const int* __restrict__ idx_i) {
    int e = blockIdx.x * blockDim.x + threadIdx.x;
    if (e < NEDGES) atomicAdd(&g_cnt[__ldg(&idx_i[e])], 1);
}

__global__ __launch_bounds__(1024) void scan_kernel() {
    __shared__ int s[1024];
    const int T = 1024;
    const int t = threadIdx.x;
    const int CH = (NATOMS + T - 1) / T;
    const int base = t * CH;

    int sum = 0;
    for (int k = 0; k < CH; k++) {
        int idx = base + k;
        if (idx < NATOMS) sum += g_cnt[idx];
    }
    s[t] = sum;
    __syncthreads();
    for (int off = 1; off < T; off <<= 1) {
        int add = (t >= off) ? s[t - off] : 0;
        __syncthreads();
        s[t] += add;
        __syncthreads();
    }
    int run = s[t] - sum;
    for (int k = 0; k < CH; k++) {
        int idx = base + k;
        if (idx < NATOMS) { g_off[idx] = run; run += g_cnt[idx]; }
    }
}

__global__ __launch_bounds__(256) void scatter_kernel(
    const int* __restrict__ idx_i, const int* __restrict__ idx_j,
    const float* __restrict__ dir_ij)
{
    int e = blockIdx.x * blockDim.x + threadIdx.x;
    if (e < NEDGES) {
        int i = __ldg(&idx_i[e]);
        int j = __ldg(&idx_j[e]);
        int pos = g_off[i] + atomicAdd(&g_cur[i], 1);
        g_pe[pos] = make_int2(e, j);
        float4 d;
        d.x = __ldg(&dir_ij[(size_t)e * 3 + 0]);
        d.y = __ldg(&dir_ij[(size_t)e * 3 + 1]);
        d.z = __ldg(&dir_ij[(size_t)e * 3 + 2]);
        d.w = 0.f;
        g_sdir[pos] = d;
    }
}

__global__ __launch_bounds__(256) void chunk_kernel() {
    int i = blockIdx.x * blockDim.x + threadIdx.x;
    if (i >= NATOMS) return;
    int cnt = g_cnt[i];
    int off = g_off[i];
    while (cnt > 0) {
        int c = cnt < CHUNK ? cnt : CHUNK;
        int pos = atomicAdd(&g_nchunks, 1);
        g_chunks[pos] = make_int2(off, (c << 16) | i);
        off += c;
        cnt -= c;
    }
}

// ---------------------------------------------------------------------------
// Kernel C: one warp per chunk; HALF-WARP per edge (2 edges per iteration).
// Lane sl in [0,16) of each half owns features {4sl..4sl+3}.
// ---------------------------------------------------------------------------
__device__ __forceinline__ void red4(float* p, float4 v) {
    asm volatile("red.global.add.v4.f32 [%0], {%1, %2, %3, %4};"
                 :: "l"(p), "f"(v.x), "f"(v.y), "f"(v.z), "f"(v.w)
                 : "memory");
}

__device__ __forceinline__ float4 h4_to_f4(uint2 u) {
    __half2 lo = *(__half2*)&u.x;
    __half2 hi = *(__half2*)&u.y;
    float2 a = __half22float2(lo);
    float2 b = __half22float2(hi);
    return make_float4(a.x, a.y, b.x, b.y);
}

__global__ __launch_bounds__(256) void painn_edge_kernel(
    const float* __restrict__ Wij, float* __restrict__ out)
{
    const int warp = (blockIdx.x * blockDim.x + threadIdx.x) >> 5;
    const int lane = threadIdx.x & 31;
    if (warp >= g_nchunks) return;

    const int sub = lane >> 4;        // 0: even edges, 1: odd edges
    const int sl  = lane & 15;        // lane within half-warp

    const int2 ck = __ldg(&g_chunks[warp]);
    const int beg = ck.x;
    const int cnt = ck.y >> 16;
    const int i   = ck.y & 0xFFFF;
    const int end = beg + cnt;

    float4 aq = make_float4(0.f, 0.f, 0.f, 0.f);
    float4 a0 = make_float4(0.f, 0.f, 0.f, 0.f);
    float4 a1 = make_float4(0.f, 0.f, 0.f, 0.f);
    float4 a2 = make_float4(0.f, 0.f, 0.f, 0.f);

#pragma unroll 2
    for (int p = beg + sub; p < end; p += 2) {
        const int2 ej = __ldg(&g_pe[p]);          // broadcast within half
        const float4 d = __ldg(&g_sdir[p]);
        const int e = ej.x, j = ej.y;

        const float4* W4 = (const float4*)(Wij + (size_t)e * 192);
        const uint2* T = (const uint2*)(g_xm + (size_t)j * 192);

        const float4 w0 = __ldg(&W4[sl]);
        const float4 w1 = __ldg(&W4[16 + sl]);
        const float4 w2 = __ldg(&W4[32 + sl]);
        const float4 x0 = h4_to_f4(__ldg(&T[sl]));
        const float4 x1 = h4_to_f4(__ldg(&T[16 + sl]));
        const float4 x2 = h4_to_f4(__ldg(&T[32 + sl]));
        const float4 m0 = h4_to_f4(__ldg(&T[48 + sl]));
        const float4 m1 = h4_to_f4(__ldg(&T[64 + sl]));
        const float4 m2 = h4_to_f4(__ldg(&T[80 + sl]));

        aq.x = fmaf(w0.x, x0.x, aq.x);
        aq.y = fmaf(w0.y, x0.y, aq.y);
        aq.z = fmaf(w0.z, x0.z, aq.z);
        aq.w = fmaf(w0.w, x0.w, aq.w);

        const float4 mR = make_float4(w1.x * x1.x, w1.y * x1.y, w1.z * x1.z, w1.w * x1.w);
        const float4 mM = make_float4(w2.x * x2.x, w2.y * x2.y, w2.z * x2.z, w2.w * x2.w);

        a0.x = fmaf(mR.x, d.x, fmaf(mM.x, m0.x, a0.x));
        a0.y = fmaf(mR.y, d.x, fmaf(mM.y, m0.y, a0.y));
        a0.z = fmaf(mR.z, d.x, fmaf(mM.z, m0.z, a0.z));
        a0.w = fmaf(mR.w, d.x, fmaf(mM.w, m0.w, a0.w));

        a1.x = fmaf(mR.x, d.y, fmaf(mM.x, m1.x, a1.x));
        a1.y = fmaf(mR.y, d.y, fmaf(mM.y, m1.y, a1.y));
        a1.z = fmaf(mR.z, d.y, fmaf(mM.z, m1.z, a1.z));
        a1.w = fmaf(mR.w, d.y, fmaf(mM.w, m1.w, a1.w));

        a2.x = fmaf(mR.x, d.z, fmaf(mM.x, m2.x, a2.x));
        a2.y = fmaf(mR.y, d.z, fmaf(mM.y, m2.y, a2.y));
        a2.z = fmaf(mR.z, d.z, fmaf(mM.z, m2.z, a2.z));
        a2.w = fmaf(mR.w, d.z, fmaf(mM.w, m2.w, a2.w));
    }

    // both halves flush to the same atom; atomics commute
    red4(out + (size_t)i * 64 + sl * 4, aq);
    float* om = out + (size_t)NATOMS * 64 + (size_t)i * 192 + sl * 4;
    red4(om,       a0);
    red4(om + 64,  a1);
    red4(om + 128, a2);
}

// ---------------------------------------------------------------------------
// launch
// ---------------------------------------------------------------------------
extern "C" void kernel_launch(void* const* d_in, const int* in_sizes, int n_in,
                              void* d_out, int out_size)
{
    int iq = -1, imu = -1, iW = -1, idir = -1, ii = -1, ij = -1;
    int iW1 = -1, ib1 = -1, iW2 = -1, ib2 = -1;
    for (int k = 0; k < n_in; k++) {
        long s = in_sizes[k];
        if      (s == (long)NATOMS * 64)   iq  = k;
        else if (s == (long)NATOMS * 192)  imu = k;
        else if (s == (long)NEDGES * 192)  iW  = k;
        else if (s == (long)NEDGES * 3)    idir = k;
        else if (s == (long)NEDGES)        { if (ii < 0) ii = k; else ij = k; }
        else if (s == 64 * 64)             iW1 = k;
        else if (s == 64)                  ib1 = k;
        else if (s == 64 * 192)            iW2 = k;
        else if (s == 192)                 ib2 = k;
    }

    const float* q   = (const float*)d_in[iq];
    const float* mu  = (const float*)d_in[imu];
    const float* Wij = (const float*)d_in[iW];
    const float* dir = (const float*)d_in[idir];
    const int*  idxi = (const int*)d_in[ii];
    const int*  idxj = (const int*)d_in[ij];
    const float* W1  = (const float*)d_in[iW1];
    const float* b1  = (const float*)d_in[ib1];
    const float* W2  = (const float*)d_in[iW2];
    const float* b2  = (const float*)d_in[ib2];
    float* out = (float*)d_out;

    // prep: sort edges by idx_i, build chunks
    zero_cnt_kernel<<<(NATOMS + 255) / 256, 256>>>();
    hist_kernel<<<(NEDGES + 255) / 256, 256>>>(idxi);
    scan_kernel<<<1, 1024>>>();
    scatter_kernel<<<(NEDGES + 255) / 256, 256>>>(idxi, idxj, dir);
    chunk_kernel<<<(NATOMS + 255) / 256, 256>>>();

    // per-atom MLP -> fp16 x part of g_xm
    painn_mlp_kernel<<<(NATOMS + 127) / 128, 256>>>(q, W1, b1, W2, b2);

    // out = concat(q, mu) + fp16 mu table
    {
        const int total2 = NATOMS * 128;
        init_fuse_kernel<<<(total2 + 255) / 256, 256>>>(q, mu, out);
    }

    // edge chunks (one warp each)
    {
        const int warps_per_block = 256 / 32;
        const int blocks = (MAXCHUNKS + warps_per_block - 1) / warps_per_block;
        painn_edge_kernel<<<blocks, 256>>>(Wij, out);
    }
}

// round 9
// speedup vs baseline: 1.0975x; 1.0679x over previous
#include <cuda_runtime.h>
#include <cuda_fp16.h>
#include <cstdint>

#define NATOMS 50000
#define NEDGES 800000

// scratch: per atom 96 half2 of x (MLP output), then 96 half2 of mu
__device__ __half2 g_xm[NATOMS * 192];

// ---- packed f32x2 helpers -------------------------------------------------
#define PK2(d, lo, hi) \
    asm("mov.b64 %0, {%1, %2};" : "=l"(d) : "r"(__float_as_uint(lo)), "r"(__float_as_uint(hi)))
#define UPK2(lo, hi, d) do { unsigned _ulo, _uhi; \
    asm("mov.b64 {%0, %1}, %2;" : "=r"(_ulo), "=r"(_uhi) : "l"(d)); \
    lo = __uint_as_float(_ulo); hi = __uint_as_float(_uhi); } while (0)
#define FMA2(acc, a, b) \
    asm("fma.rn.f32x2 %0, %1, %2, %0;" : "+l"(acc) : "l"(a), "l"(b))

#define HSTRIDE 68

// ---------------------------------------------------------------------------
// Kernel A: per-atom MLP  x = W2 * silu(W1*q + b1) + b2  -> fp16 g_xm[:,0:96]
// ---------------------------------------------------------------------------
__global__ __launch_bounds__(256) void painn_mlp_kernel(
    const float* __restrict__ q,
    const float* __restrict__ W1, const float* __restrict__ b1,
    const float* __restrict__ W2, const float* __restrict__ b2)
{
    __shared__ float sH[128 * HSTRIDE];
    __shared__ float sB2[192];

    const int t = threadIdx.x;
    const int atom0 = blockIdx.x * 128;
    const int tx = t & 15;
    const int ty = t >> 4;

    for (int k = t; k < 128 * 16; k += 256) {
        int a = k >> 4, c4 = k & 15;
        int ga = atom0 + a;
        float4 v = (ga < NATOMS) ? __ldg((const float4*)q + (size_t)ga * 16 + c4)
                                 : make_float4(0.f, 0.f, 0.f, 0.f);
        *(float4*)&sH[a * HSTRIDE + c4 * 4] = v;
    }
    if (t < 192) sB2[t] = b2[t];
    __syncthreads();

    unsigned long long acc1[8][2];
#pragma unroll
    for (int r = 0; r < 8; r++) { acc1[r][0] = 0ull; acc1[r][1] = 0ull; }

    const float4* W1v = (const float4*)W1;
#pragma unroll 4
    for (int k = 0; k < 64; k++) {
        float4 w = __ldg(&W1v[k * 16 + tx]);
        unsigned long long wp0, wp1;
        PK2(wp0, w.x, w.y);
        PK2(wp1, w.z, w.w);
#pragma unroll
        for (int r = 0; r < 8; r++) {
            float h = sH[(ty * 8 + r) * HSTRIDE + k];
            unsigned long long hp;
            PK2(hp, h, h);
            FMA2(acc1[r][0], hp, wp0);
            FMA2(acc1[r][1], hp, wp1);
        }
    }
    __syncthreads();

    {
        float b0 = __ldg(&b1[tx * 4 + 0]);
        float bb1 = __ldg(&b1[tx * 4 + 1]);
        float b2v = __ldg(&b1[tx * 4 + 2]);
        float b3 = __ldg(&b1[tx * 4 + 3]);
#pragma unroll
        for (int r = 0; r < 8; r++) {
            float v0, v1, v2, v3;
            UPK2(v0, v1, acc1[r][0]);
            UPK2(v2, v3, acc1[r][1]);
            v0 += b0; v1 += bb1; v2 += b2v; v3 += b3;
            v0 = v0 / (1.0f + __expf(-v0));
            v1 = v1 / (1.0f + __expf(-v1));
            v2 = v2 / (1.0f + __expf(-v2));
            v3 = v3 / (1.0f + __expf(-v3));
            float* row = &sH[(ty * 8 + r) * HSTRIDE + tx * 4];
            row[0] = v0; row[1] = v1; row[2] = v2; row[3] = v3;
        }
    }
    __syncthreads();

    unsigned long long a2[8][6];
#pragma unroll
    for (int r = 0; r < 8; r++)
#pragma unroll
        for (int c = 0; c < 6; c++) a2[r][c] = 0ull;

    const float4* W2v = (const float4*)W2;
    const int oc4 = tx * 3;
#pragma unroll 2
    for (int k = 0; k < 64; k++) {
        float4 wa = __ldg(&W2v[k * 48 + oc4 + 0]);
        float4 wb = __ldg(&W2v[k * 48 + oc4 + 1]);
        float4 wc = __ldg(&W2v[k * 48 + oc4 + 2]);
        unsigned long long w0, w1, w2, w3, w4, w5;
        PK2(w0, wa.x, wa.y); PK2(w1, wa.z, wa.w);
        PK2(w2, wb.x, wb.y); PK2(w3, wb.z, wb.w);
        PK2(w4, wc.x, wc.y); PK2(w5, wc.z, wc.w);
#pragma unroll
        for (int r = 0; r < 8; r++) {
            float h = sH[(ty * 8 + r) * HSTRIDE + k];
            unsigned long long hp;
            PK2(hp, h, h);
            FMA2(a2[r][0], hp, w0);
            FMA2(a2[r][1], hp, w1);
            FMA2(a2[r][2], hp, w2);
            FMA2(a2[r][3], hp, w3);
            FMA2(a2[r][4], hp, w4);
            FMA2(a2[r][5], hp, w5);
        }
    }

    const int ocol = tx * 12;
#pragma unroll
    for (int r = 0; r < 8; r++) {
        int atom = atom0 + ty * 8 + r;
        if (atom < NATOMS) {
            float v[12];
#pragma unroll
            for (int c = 0; c < 6; c++) UPK2(v[2 * c], v[2 * c + 1], a2[r][c]);
            __half2* dst = &g_xm[(size_t)atom * 192 + tx * 6];
#pragma unroll
            for (int c = 0; c < 6; c++) {
                dst[c] = __floats2half2_rn(v[2 * c] + sB2[ocol + 2 * c],
                                           v[2 * c + 1] + sB2[ocol + 2 * c + 1]);
            }
        }
    }
}

// ---------------------------------------------------------------------------
// Fused: out = concat(q, mu)  AND  g_xm[:,96:192] = fp16(mu)
// ---------------------------------------------------------------------------
__global__ __launch_bounds__(256) void init_fuse_kernel(
    const float* __restrict__ q, const float* __restrict__ mu,
    float* __restrict__ out)
{
    const int NQ2 = NATOMS * 32;
    const int NT2 = NATOMS * 128;
    int i = blockIdx.x * blockDim.x + threadIdx.x;
    if (i < NQ2) {
        ((float2*)out)[i] = ((const float2*)q)[i];
    } else if (i < NT2) {
        int m = i - NQ2;
        float2 v = __ldg((const float2*)mu + m);
        ((float2*)out)[i] = v;
        g_xm[(size_t)(m / 96) * 192 + 96 + (m % 96)] = __floats2half2_rn(v.x, v.y);
    }
}

// ---------------------------------------------------------------------------
// Kernel C: edges in ORIGINAL order (coalesced Wij/dir/idx streaming).
// Half-warp per edge: lanes 0-15 even edges, 16-31 odd edges; lane sl owns
// features {4sl..4sl+3}. red.global.add.v4 scatter into out.
// ---------------------------------------------------------------------------
__device__ __forceinline__ void red4(float* p, float4 v) {
    asm volatile("red.global.add.v4.f32 [%0], {%1, %2, %3, %4};"
                 :: "l"(p), "f"(v.x), "f"(v.y), "f"(v.z), "f"(v.w)
                 : "memory");
}

__device__ __forceinline__ float4 h4_to_f4(uint2 u) {
    __half2 lo = *(__half2*)&u.x;
    __half2 hi = *(__half2*)&u.y;
    float2 a = __half22float2(lo);
    float2 b = __half22float2(hi);
    return make_float4(a.x, a.y, b.x, b.y);
}

__global__ __launch_bounds__(256) void painn_edge_kernel(
    const float* __restrict__ Wij, const float* __restrict__ dir_ij,
    const int* __restrict__ idx_i, const int* __restrict__ idx_j,
    float* __restrict__ out)
{
    const int warp = (blockIdx.x * blockDim.x + threadIdx.x) >> 5;
    const int lane = threadIdx.x & 31;
    const int sub = lane >> 4;
    const int sl  = lane & 15;

    const int e0 = warp * 16;          // 16 edges per warp, 2 per iteration
    if (e0 >= NEDGES) return;

#pragma unroll 4
    for (int e = e0 + sub; e < e0 + 16; e += 2) {
        const int i = __ldg(&idx_i[e]);      // broadcast within half-warp
        const int j = __ldg(&idx_j[e]);

        const float dx = __ldg(&dir_ij[(size_t)e * 3 + 0]);
        const float dy = __ldg(&dir_ij[(size_t)e * 3 + 1]);
        const float dz = __ldg(&dir_ij[(size_t)e * 3 + 2]);

        const float4* W4 = (const float4*)(Wij + (size_t)e * 192);
        const uint2* T = (const uint2*)(g_xm + (size_t)j * 192);

        const float4 w0 = __ldg(&W4[sl]);
        const float4 w1 = __ldg(&W4[16 + sl]);
        const float4 w2 = __ldg(&W4[32 + sl]);
        const float4 x0 = h4_to_f4(__ldg(&T[sl]));
        const float4 x1 = h4_to_f4(__ldg(&T[16 + sl]));
        const float4 x2 = h4_to_f4(__ldg(&T[32 + sl]));
        const float4 m0 = h4_to_f4(__ldg(&T[48 + sl]));
        const float4 m1 = h4_to_f4(__ldg(&T[64 + sl]));
        const float4 m2 = h4_to_f4(__ldg(&T[80 + sl]));

        float4 dq;
        dq.x = w0.x * x0.x; dq.y = w0.y * x0.y;
        dq.z = w0.z * x0.z; dq.w = w0.w * x0.w;

        const float4 mR = make_float4(w1.x * x1.x, w1.y * x1.y, w1.z * x1.z, w1.w * x1.w);
        const float4 mM = make_float4(w2.x * x2.x, w2.y * x2.y, w2.z * x2.z, w2.w * x2.w);

        float4 d0, d1, d2;
        d0.x = fmaf(mR.x, dx, mM.x * m0.x); d0.y = fmaf(mR.y, dx, mM.y * m0.y);
        d0.z = fmaf(mR.z, dx, mM.z * m0.z); d0.w = fmaf(mR.w, dx, mM.w * m0.w);
        d1.x = fmaf(mR.x, dy, mM.x * m1.x); d1.y = fmaf(mR.y, dy, mM.y * m1.y);
        d1.z = fmaf(mR.z, dy, mM.z * m1.z); d1.w = fmaf(mR.w, dy, mM.w * m1.w);
        d2.x = fmaf(mR.x, dz, mM.x * m2.x); d2.y = fmaf(mR.y, dz, mM.y * m2.y);
        d2.z = fmaf(mR.z, dz, mM.z * m2.z); d2.w = fmaf(mR.w, dz, mM.w * m2.w);

        red4(out + (size_t)i * 64 + sl * 4, dq);
        float* om = out + (size_t)NATOMS * 64 + (size_t)i * 192 + sl * 4;
        red4(om,       d0);
        red4(om + 64,  d1);
        red4(om + 128, d2);
    }
}

// ---------------------------------------------------------------------------
// launch
// ---------------------------------------------------------------------------
extern "C" void kernel_launch(void* const* d_in, const int* in_sizes, int n_in,
                              void* d_out, int out_size)
{
    int iq = -1, imu = -1, iW = -1, idir = -1, ii = -1, ij = -1;
    int iW1 = -1, ib1 = -1, iW2 = -1, ib2 = -1;
    for (int k = 0; k < n_in; k++) {
        long s = in_sizes[k];
        if      (s == (long)NATOMS * 64)   iq  = k;
        else if (s == (long)NATOMS * 192)  imu = k;
        else if (s == (long)NEDGES * 192)  iW  = k;
        else if (s == (long)NEDGES * 3)    idir = k;
        else if (s == (long)NEDGES)        { if (ii < 0) ii = k; else ij = k; }
        else if (s == 64 * 64)             iW1 = k;
        else if (s == 64)                  ib1 = k;
        else if (s == 64 * 192)            iW2 = k;
        else if (s == 192)                 ib2 = k;
    }

    const float* q   = (const float*)d_in[iq];
    const float* mu  = (const float*)d_in[imu];
    const float* Wij = (const float*)d_in[iW];
    const float* dir = (const float*)d_in[idir];
    const int*  idxi = (const int*)d_in[ii];
    const int*  idxj = (const int*)d_in[ij];
    const float* W1  = (const float*)d_in[iW1];
    const float* b1  = (const float*)d_in[ib1];
    const float* W2  = (const float*)d_in[iW2];
    const float* b2  = (const float*)d_in[ib2];
    float* out = (float*)d_out;

    // per-atom MLP -> fp16 x part of g_xm
    painn_mlp_kernel<<<(NATOMS + 127) / 128, 256>>>(q, W1, b1, W2, b2);

    // out = concat(q, mu) + fp16 mu table
    {
        const int total2 = NATOMS * 128;
        init_fuse_kernel<<<(total2 + 255) / 256, 256>>>(q, mu, out);
    }

    // edge scatter in original order (16 edges per warp)
    {
        const int warps = (NEDGES + 15) / 16;
        const int blocks = (warps * 32 + 255) / 256;
        painn_edge_kernel<<<blocks, 256>>>(Wij, dir, idxi, idxj, out);
    }
}

// round 10
// speedup vs baseline: 1.1034x; 1.0054x over previous
#include <cuda_runtime.h>
#include <cuda_fp16.h>
#include <cstdint>

#define NATOMS 50000
#define NEDGES 800000

// scratch: per atom 96 half2 of x (MLP output), then 96 half2 of mu
__device__ __half2 g_xm[NATOMS * 192];

// ---- packed f32x2 helpers -------------------------------------------------
#define PK2(d, lo, hi) \
    asm("mov.b64 %0, {%1, %2};" : "=l"(d) : "r"(__float_as_uint(lo)), "r"(__float_as_uint(hi)))
#define UPK2(lo, hi, d) do { unsigned _ulo, _uhi; \
    asm("mov.b64 {%0, %1}, %2;" : "=r"(_ulo), "=r"(_uhi) : "l"(d)); \
    lo = __uint_as_float(_ulo); hi = __uint_as_float(_uhi); } while (0)
#define FMA2(acc, a, b) \
    asm("fma.rn.f32x2 %0, %1, %2, %0;" : "+l"(acc) : "l"(a), "l"(b))

#define HSTRIDE 68

// ---------------------------------------------------------------------------
// Kernel A: per-atom MLP  x = W2 * silu(W1*q + b1) + b2  -> fp16 g_xm[:,0:96]
// __launch_bounds__(256, 2): cap at 128 regs so 2 CTAs/SM fit (occupancy fix).
// ---------------------------------------------------------------------------
__global__ __launch_bounds__(256, 2) void painn_mlp_kernel(
    const float* __restrict__ q,
    const float* __restrict__ W1, const float* __restrict__ b1,
    const float* __restrict__ W2, const float* __restrict__ b2)
{
    __shared__ float sH[128 * HSTRIDE];
    __shared__ float sB2[192];

    const int t = threadIdx.x;
    const int atom0 = blockIdx.x * 128;
    const int tx = t & 15;
    const int ty = t >> 4;

    for (int k = t; k < 128 * 16; k += 256) {
        int a = k >> 4, c4 = k & 15;
        int ga = atom0 + a;
        float4 v = (ga < NATOMS) ? __ldg((const float4*)q + (size_t)ga * 16 + c4)
                                 : make_float4(0.f, 0.f, 0.f, 0.f);
        *(float4*)&sH[a * HSTRIDE + c4 * 4] = v;
    }
    if (t < 192) sB2[t] = b2[t];
    __syncthreads();

    unsigned long long acc1[8][2];
#pragma unroll
    for (int r = 0; r < 8; r++) { acc1[r][0] = 0ull; acc1[r][1] = 0ull; }

    const float4* W1v = (const float4*)W1;
#pragma unroll 4
    for (int k = 0; k < 64; k++) {
        float4 w = __ldg(&W1v[k * 16 + tx]);
        unsigned long long wp0, wp1;
        PK2(wp0, w.x, w.y);
        PK2(wp1, w.z, w.w);
#pragma unroll
        for (int r = 0; r < 8; r++) {
            float h = sH[(ty * 8 + r) * HSTRIDE + k];
            unsigned long long hp;
            PK2(hp, h, h);
            FMA2(acc1[r][0], hp, wp0);
            FMA2(acc1[r][1], hp, wp1);
        }
    }
    __syncthreads();

    {
        float b0 = __ldg(&b1[tx * 4 + 0]);
        float bb1 = __ldg(&b1[tx * 4 + 1]);
        float b2v = __ldg(&b1[tx * 4 + 2]);
        float b3 = __ldg(&b1[tx * 4 + 3]);
#pragma unroll
        for (int r = 0; r < 8; r++) {
            float v0, v1, v2, v3;
            UPK2(v0, v1, acc1[r][0]);
            UPK2(v2, v3, acc1[r][1]);
            v0 += b0; v1 += bb1; v2 += b2v; v3 += b3;
            v0 = v0 / (1.0f + __expf(-v0));
            v1 = v1 / (1.0f + __expf(-v1));
            v2 = v2 / (1.0f + __expf(-v2));
            v3 = v3 / (1.0f + __expf(-v3));
            float* row = &sH[(ty * 8 + r) * HSTRIDE + tx * 4];
            row[0] = v0; row[1] = v1; row[2] = v2; row[3] = v3;
        }
    }
    __syncthreads();

    unsigned long long a2[8][6];
#pragma unroll
    for (int r = 0; r < 8; r++)
#pragma unroll
        for (int c = 0; c < 6; c++) a2[r][c] = 0ull;

    const float4* W2v = (const float4*)W2;
    const int oc4 = tx * 3;
#pragma unroll 2
    for (int k = 0; k < 64; k++) {
        float4 wa = __ldg(&W2v[k * 48 + oc4 + 0]);
        float4 wb = __ldg(&W2v[k * 48 + oc4 + 1]);
        float4 wc = __ldg(&W2v[k * 48 + oc4 + 2]);
        unsigned long long w0, w1, w2, w3, w4, w5;
        PK2(w0, wa.x, wa.y); PK2(w1, wa.z, wa.w);
        PK2(w2, wb.x, wb.y); PK2(w3, wb.z, wb.w);
        PK2(w4, wc.x, wc.y); PK2(w5, wc.z, wc.w);
#pragma unroll
        for (int r = 0; r < 8; r++) {
            float h = sH[(ty * 8 + r) * HSTRIDE + k];
            unsigned long long hp;
            PK2(hp, h, h);
            FMA2(a2[r][0], hp, w0);
            FMA2(a2[r][1], hp, w1);
            FMA2(a2[r][2], hp, w2);
            FMA2(a2[r][3], hp, w3);
            FMA2(a2[r][4], hp, w4);
            FMA2(a2[r][5], hp, w5);
        }
    }

    const int ocol = tx * 12;
#pragma unroll
    for (int r = 0; r < 8; r++) {
        int atom = atom0 + ty * 8 + r;
        if (atom < NATOMS) {
            float v[12];
#pragma unroll
            for (int c = 0; c < 6; c++) UPK2(v[2 * c], v[2 * c + 1], a2[r][c]);
            __half2* dst = &g_xm[(size_t)atom * 192 + tx * 6];
#pragma unroll
            for (int c = 0; c < 6; c++) {
                dst[c] = __floats2half2_rn(v[2 * c] + sB2[ocol + 2 * c],
                                           v[2 * c + 1] + sB2[ocol + 2 * c + 1]);
            }
        }
    }
}

// ---------------------------------------------------------------------------
// Fused: out = concat(q, mu)  AND  g_xm[:,96:192] = fp16(mu)
// ---------------------------------------------------------------------------
__global__ __launch_bounds__(256) void init_fuse_kernel(
    const float* __restrict__ q, const float* __restrict__ mu,
    float* __restrict__ out)
{
    const int NQ2 = NATOMS * 32;
    const int NT2 = NATOMS * 128;
    int i = blockIdx.x * blockDim.x + threadIdx.x;
    if (i < NQ2) {
        ((float2*)out)[i] = ((const float2*)q)[i];
    } else if (i < NT2) {
        int m = i - NQ2;
        float2 v = __ldg((const float2*)mu + m);
        ((float2*)out)[i] = v;
        g_xm[(size_t)(m / 96) * 192 + 96 + (m % 96)] = __floats2half2_rn(v.x, v.y);
    }
}

// ---------------------------------------------------------------------------
// Kernel C: edges in original order. Half-warp per edge; lane sl owns
// features {4sl..4sl+3}. red.global.add.v4 scatter into out.
// ---------------------------------------------------------------------------
__device__ __forceinline__ void red4(float* p, float4 v) {
    asm volatile("red.global.add.v4.f32 [%0], {%1, %2, %3, %4};"
                 :: "l"(p), "f"(v.x), "f"(v.y), "f"(v.z), "f"(v.w)
                 : "memory");
}

__device__ __forceinline__ float4 h4_to_f4(uint2 u) {
    __half2 lo = *(__half2*)&u.x;
    __half2 hi = *(__half2*)&u.y;
    float2 a = __half22float2(lo);
    float2 b = __half22float2(hi);
    return make_float4(a.x, a.y, b.x, b.y);
}

__global__ __launch_bounds__(256) void painn_edge_kernel(
    const float* __restrict__ Wij, const float* __restrict__ dir_ij,
    const int* __restrict__ idx_i, const int* __restrict__ idx_j,
    float* __restrict__ out)
{
    const int warp = (blockIdx.x * blockDim.x + threadIdx.x) >> 5;
    const int lane = threadIdx.x & 31;
    const int sub = lane >> 4;
    const int sl  = lane & 15;

    const int e0 = warp * 16;
    if (e0 >= NEDGES) return;

#pragma unroll 4
    for (int e = e0 + sub; e < e0 + 16; e += 2) {
        const int i = __ldg(&idx_i[e]);
        const int j = __ldg(&idx_j[e]);

        const float dx = __ldg(&dir_ij[(size_t)e * 3 + 0]);
        const float dy = __ldg(&dir_ij[(size_t)e * 3 + 1]);
        const float dz = __ldg(&dir_ij[(size_t)e * 3 + 2]);

        const float4* W4 = (const float4*)(Wij + (size_t)e * 192);
        const uint2* T = (const uint2*)(g_xm + (size_t)j * 192);

        const float4 w0 = __ldg(&W4[sl]);
        const float4 w1 = __ldg(&W4[16 + sl]);
        const float4 w2 = __ldg(&W4[32 + sl]);
        const float4 x0 = h4_to_f4(__ldg(&T[sl]));
        const float4 x1 = h4_to_f4(__ldg(&T[16 + sl]));
        const float4 x2 = h4_to_f4(__ldg(&T[32 + sl]));
        const float4 m0 = h4_to_f4(__ldg(&T[48 + sl]));
        const float4 m1 = h4_to_f4(__ldg(&T[64 + sl]));
        const float4 m2 = h4_to_f4(__ldg(&T[80 + sl]));

        float4 dq;
        dq.x = w0.x * x0.x; dq.y = w0.y * x0.y;
        dq.z = w0.z * x0.z; dq.w = w0.w * x0.w;

        const float4 mR = make_float4(w1.x * x1.x, w1.y * x1.y, w1.z * x1.z, w1.w * x1.w);
        const float4 mM = make_float4(w2.x * x2.x, w2.y * x2.y, w2.z * x2.z, w2.w * x2.w);

        float4 d0, d1, d2;
        d0.x = fmaf(mR.x, dx, mM.x * m0.x); d0.y = fmaf(mR.y, dx, mM.y * m0.y);
        d0.z = fmaf(mR.z, dx, mM.z * m0.z); d0.w = fmaf(mR.w, dx, mM.w * m0.w);
        d1.x = fmaf(mR.x, dy, mM.x * m1.x); d1.y = fmaf(mR.y, dy, mM.y * m1.y);
        d1.z = fmaf(mR.z, dy, mM.z * m1.z); d1.w = fmaf(mR.w, dy, mM.w * m1.w);
        d2.x = fmaf(mR.x, dz, mM.x * m2.x); d2.y = fmaf(mR.y, dz, mM.y * m2.y);
        d2.z = fmaf(mR.z, dz, mM.z * m2.z); d2.w = fmaf(mR.w, dz, mM.w * m2.w);

        red4(out + (size_t)i * 64 + sl * 4, dq);
        float* om = out + (size_t)NATOMS * 64 + (size_t)i * 192 + sl * 4;
        red4(om,       d0);
        red4(om + 64,  d1);
        red4(om + 128, d2);
    }
}

// ---------------------------------------------------------------------------
// launch
// ---------------------------------------------------------------------------
extern "C" void kernel_launch(void* const* d_in, const int* in_sizes, int n_in,
                              void* d_out, int out_size)
{
    int iq = -1, imu = -1, iW = -1, idir = -1, ii = -1, ij = -1;
    int iW1 = -1, ib1 = -1, iW2 = -1, ib2 = -1;
    for (int k = 0; k < n_in; k++) {
        long s = in_sizes[k];
        if      (s == (long)NATOMS * 64)   iq  = k;
        else if (s == (long)NATOMS * 192)  imu = k;
        else if (s == (long)NEDGES * 192)  iW  = k;
        else if (s == (long)NEDGES * 3)    idir = k;
        else if (s == (long)NEDGES)        { if (ii < 0) ii = k; else ij = k; }
        else if (s == 64 * 64)             iW1 = k;
        else if (s == 64)                  ib1 = k;
        else if (s == 64 * 192)            iW2 = k;
        else if (s == 192)                 ib2 = k;
    }

    const float* q   = (const float*)d_in[iq];
    const float* mu  = (const float*)d_in[imu];
    const float* Wij = (const float*)d_in[iW];
    const float* dir = (const float*)d_in[idir];
    const int*  idxi = (const int*)d_in[ii];
    const int*  idxj = (const int*)d_in[ij];
    const float* W1  = (const float*)d_in[iW1];
    const float* b1  = (const float*)d_in[ib1];
    const float* W2  = (const float*)d_in[iW2];
    const float* b2  = (const float*)d_in[ib2];
    float* out = (float*)d_out;

    // per-atom MLP -> fp16 x part of g_xm
    painn_mlp_kernel<<<(NATOMS + 127) / 128, 256>>>(q, W1, b1, W2, b2);

    // out = concat(q, mu) + fp16 mu table
    {
        const int total2 = NATOMS * 128;
        init_fuse_kernel<<<(total2 + 255) / 256, 256>>>(q, mu, out);
    }

    // edge scatter in original order (16 edges per warp)
    {
        const int warps = (NEDGES + 15) / 16;
        const int blocks = (warps * 32 + 255) / 256;
        painn_edge_kernel<<<blocks, 256>>>(Wij, dir, idxi, idxj, out);
    }
}

// round 11
// speedup vs baseline: 1.3455x; 1.2194x over previous
#include <cuda_runtime.h>
#include <cuda_fp16.h>
#include <cstdint>

#define NATOMS 50000
#define NEDGES 800000

// scratch: per atom 96 half2 of x (MLP output), then 96 half2 of mu
__device__ __half2 g_xm[NATOMS * 192];

// ---------------------------------------------------------------------------
// helpers
// ---------------------------------------------------------------------------
__device__ __forceinline__ uint32_t smaddr(const void* p) {
    return (uint32_t)__cvta_generic_to_shared(p);
}
__device__ __forceinline__ uint32_t f2h2(float a, float b) {
    __half2 h = __floats2half2_rn(a, b);
    return *reinterpret_cast<uint32_t*>(&h);
}
__device__ __forceinline__ float silu(float v) {
    return v / (1.0f + __expf(-v));
}

// ---------------------------------------------------------------------------
// Kernel A: per-atom MLP on tensor cores.
//   x = W2 * silu(W1*q + b1) + b2   -> fp16 into g_xm[:,0:96]
// 256 threads = 8 warps; block does 128 atoms (warp w -> rows 16w..16w+15).
// Phase 1 A-fragments loaded straight from global q (float2 -> half2).
// W1/W2 staged in XOR-swizzled smem (8-half blocks), conflict-free ldmatrix.
// ---------------------------------------------------------------------------
__global__ __launch_bounds__(256) void painn_mlp_tc(
    const float* __restrict__ q,
    const float* __restrict__ W1, const float* __restrict__ b1,
    const float* __restrict__ W2, const float* __restrict__ b2)
{
    __shared__ __half sH[128 * 64];    // 16384 B (written phase1, read phase2)
    __shared__ __half sW1[64 * 64];    //  8192 B
    __shared__ __half sW2[64 * 192];   // 24576 B   (total exactly 48 KB)

    const int t = threadIdx.x;
    const int atom0 = blockIdx.x * 128;

    // stage W1 (swizzle: 8-half block b at row r goes to block b^(r&7))
    for (int idx = t; idx < 64 * 16; idx += 256) {
        int r = idx >> 4, c4 = idx & 15;          // c4: float4 within row
        float4 v = __ldg((const float4*)W1 + r * 16 + c4);
        int blk = (c4 >> 1) ^ (r & 7);
        __half2* d = (__half2*)&sW1[r * 64 + blk * 8 + (c4 & 1) * 4];
        d[0] = __floats2half2_rn(v.x, v.y);
        d[1] = __floats2half2_rn(v.z, v.w);
    }
    // stage W2
    for (int idx = t; idx < 64 * 48; idx += 256) {
        int r = idx / 48, c4 = idx % 48;
        float4 v = __ldg((const float4*)W2 + r * 48 + c4);
        int blk = (c4 >> 1) ^ (r & 7);
        __half2* d = (__half2*)&sW2[r * 192 + blk * 8 + (c4 & 1) * 4];
        d[0] = __floats2half2_rn(v.x, v.y);
        d[1] = __floats2half2_rn(v.z, v.w);
    }
    __syncthreads();

    const int w    = t >> 5;
    const int lane = t & 31;
    const int r    = lane >> 2;          // 0..7
    const int cc   = (lane & 3) * 2;     // 0,2,4,6

    // ---- phase 1 A fragments straight from q ----
    uint32_t A[4][4];
    {
        const int row0 = atom0 + w * 16 + r;
        const int row1 = row0 + 8;
        const bool v0 = row0 < NATOMS, v1 = row1 < NATOMS;
        const float2* q0 = (const float2*)(q + (size_t)row0 * 64);
        const float2* q1 = (const float2*)(q + (size_t)row1 * 64);
#pragma unroll
        for (int kt = 0; kt < 4; kt++) {
            int k2 = kt * 8 + (cc >> 1);                 // float2 index of k
            float2 f0 = v0 ? __ldg(&q0[k2])     : make_float2(0.f, 0.f);
            float2 f1 = v1 ? __ldg(&q1[k2])     : make_float2(0.f, 0.f);
            float2 f2 = v0 ? __ldg(&q0[k2 + 4]) : make_float2(0.f, 0.f);
            float2 f3 = v1 ? __ldg(&q1[k2 + 4]) : make_float2(0.f, 0.f);
            A[kt][0] = f2h2(f0.x, f0.y);
            A[kt][1] = f2h2(f1.x, f1.y);
            A[kt][2] = f2h2(f2.x, f2.y);
            A[kt][3] = f2h2(f3.x, f3.y);
        }
    }

    // ---- phase 1: H = silu(q*W1 + b1) ----
    const int lrow = lane & 15;
#pragma unroll
    for (int nt = 0; nt < 8; nt++) {
        float c0 = 0.f, c1 = 0.f, c2 = 0.f, c3 = 0.f;
#pragma unroll
        for (int kt = 0; kt < 4; kt++) {
            int row = kt * 16 + lrow;
            int blk = nt ^ (row & 7);
            uint32_t addr = smaddr(&sW1[row * 64 + blk * 8]);
            uint32_t b0, b1r;
            asm volatile("ldmatrix.sync.aligned.m8n8.x2.trans.shared.b16 {%0,%1}, [%2];"
                         : "=r"(b0), "=r"(b1r) : "r"(addr));
            asm volatile("mma.sync.aligned.m16n8k16.row.col.f32.f16.f16.f32 "
                         "{%0,%1,%2,%3}, {%4,%5,%6,%7}, {%8,%9}, {%0,%1,%2,%3};"
                         : "+f"(c0), "+f"(c1), "+f"(c2), "+f"(c3)
                         : "r"(A[kt][0]), "r"(A[kt][1]), "r"(A[kt][2]), "r"(A[kt][3]),
                           "r"(b0), "r"(b1r));
        }
        int col = nt * 8 + cc;
        float bb0 = __ldg(&b1[col]), bb1 = __ldg(&b1[col + 1]);
        int hr0 = w * 16 + r, hr1 = hr0 + 8;
        int blk = nt ^ (r & 7);            // (hr & 7) == (r & 7) for both rows
        *(__half2*)&sH[hr0 * 64 + blk * 8 + cc] =
            __floats2half2_rn(silu(c0 + bb0), silu(c1 + bb1));
        *(__half2*)&sH[hr1 * 64 + blk * 8 + cc] =
            __floats2half2_rn(silu(c2 + bb0), silu(c3 + bb1));
    }
    __syncwarp();

    // ---- phase 2 A fragments from sH (own rows only) ----
    uint32_t H[4][4];
#pragma unroll
    for (int kt = 0; kt < 4; kt++) {
        int row = w * 16 + lrow;
        int blk = (kt * 2 + (lane >> 4)) ^ (row & 7);
        uint32_t addr = smaddr(&sH[row * 64 + blk * 8]);
        asm volatile("ldmatrix.sync.aligned.m8n8.x4.shared.b16 {%0,%1,%2,%3}, [%4];"
                     : "=r"(H[kt][0]), "=r"(H[kt][1]), "=r"(H[kt][2]), "=r"(H[kt][3])
                     : "r"(addr));
    }

    // ---- phase 2: x = H*W2 + b2 -> g_xm fp16 ----
    const int row0 = atom0 + w * 16 + r;
    const int row1 = row0 + 8;
#pragma unroll
    for (int nt = 0; nt < 24; nt++) {
        float c0 = 0.f, c1 = 0.f, c2 = 0.f, c3 = 0.f;
#pragma unroll
        for (int kt = 0; kt < 4; kt++) {
            int row = kt * 16 + lrow;
            int blk = nt ^ (row & 7);
            uint32_t addr = smaddr(&sW2[row * 192 + blk * 8]);
            uint32_t b0, b1r;
            asm volatile("ldmatrix.sync.aligned.m8n8.x2.trans.shared.b16 {%0,%1}, [%2];"
                         : "=r"(b0), "=r"(b1r) : "r"(addr));
            asm volatile("mma.sync.aligned.m16n8k16.row.col.f32.f16.f16.f32 "
                         "{%0,%1,%2,%3}, {%4,%5,%6,%7}, {%8,%9}, {%0,%1,%2,%3};"
                         : "+f"(c0), "+f"(c1), "+f"(c2), "+f"(c3)
                         : "r"(H[kt][0]), "r"(H[kt][1]), "r"(H[kt][2]), "r"(H[kt][3]),
                           "r"(b0), "r"(b1r));
        }
        int col = nt * 8 + cc;
        float bb0 = __ldg(&b2[col]), bb1 = __ldg(&b2[col + 1]);
        if (row0 < NATOMS)
            g_xm[(size_t)row0 * 192 + (col >> 1)] = __floats2half2_rn(c0 + bb0, c1 + bb1);
        if (row1 < NATOMS)
            g_xm[(size_t)row1 * 192 + (col >> 1)] = __floats2half2_rn(c2 + bb0, c3 + bb1);
    }
}

// ---------------------------------------------------------------------------
// Fused: out = concat(q, mu)  AND  g_xm[:,96:192] = fp16(mu)
// ---------------------------------------------------------------------------
__global__ __launch_bounds__(256) void init_fuse_kernel(
    const float* __restrict__ q, const float* __restrict__ mu,
    float* __restrict__ out)
{
    const int NQ2 = NATOMS * 32;
    const int NT2 = NATOMS * 128;
    int i = blockIdx.x * blockDim.x + threadIdx.x;
    if (i < NQ2) {
        ((float2*)out)[i] = ((const float2*)q)[i];
    } else if (i < NT2) {
        int m = i - NQ2;
        float2 v = __ldg((const float2*)mu + m);
        ((float2*)out)[i] = v;
        g_xm[(size_t)(m / 96) * 192 + 96 + (m % 96)] = __floats2half2_rn(v.x, v.y);
    }
}

// ---------------------------------------------------------------------------
// Kernel C: edges in original order. Half-warp per edge; lane sl owns
// features {4sl..4sl+3}. red.global.add.v4 scatter into out.
// ---------------------------------------------------------------------------
__device__ __forceinline__ void red4(float* p, float4 v) {
    asm volatile("red.global.add.v4.f32 [%0], {%1, %2, %3, %4};"
                 :: "l"(p), "f"(v.x), "f"(v.y), "f"(v.z), "f"(v.w)
                 : "memory");
}

__device__ __forceinline__ float4 h4_to_f4(uint2 u) {
    __half2 lo = *(__half2*)&u.x;
    __half2 hi = *(__half2*)&u.y;
    float2 a = __half22float2(lo);
    float2 b = __half22float2(hi);
    return make_float4(a.x, a.y, b.x, b.y);
}

__global__ __launch_bounds__(256) void painn_edge_kernel(
    const float* __restrict__ Wij, const float* __restrict__ dir_ij,
    const int* __restrict__ idx_i, const int* __restrict__ idx_j,
    float* __restrict__ out)
{
    const int warp = (blockIdx.x * blockDim.x + threadIdx.x) >> 5;
    const int lane = threadIdx.x & 31;
    const int sub = lane >> 4;
    const int sl  = lane & 15;

    const int e0 = warp * 16;
    if (e0 >= NEDGES) return;

#pragma unroll 4
    for (int e = e0 + sub; e < e0 + 16; e += 2) {
        const int i = __ldg(&idx_i[e]);
        const int j = __ldg(&idx_j[e]);

        const float dx = __ldg(&dir_ij[(size_t)e * 3 + 0]);
        const float dy = __ldg(&dir_ij[(size_t)e * 3 + 1]);
        const float dz = __ldg(&dir_ij[(size_t)e * 3 + 2]);

        const float4* W4 = (const float4*)(Wij + (size_t)e * 192);
        const uint2* T = (const uint2*)(g_xm + (size_t)j * 192);

        const float4 w0 = __ldg(&W4[sl]);
        const float4 w1 = __ldg(&W4[16 + sl]);
        const float4 w2 = __ldg(&W4[32 + sl]);
        const float4 x0 = h4_to_f4(__ldg(&T[sl]));
        const float4 x1 = h4_to_f4(__ldg(&T[16 + sl]));
        const float4 x2 = h4_to_f4(__ldg(&T[32 + sl]));
        const float4 m0 = h4_to_f4(__ldg(&T[48 + sl]));
        const float4 m1 = h4_to_f4(__ldg(&T[64 + sl]));
        const float4 m2 = h4_to_f4(__ldg(&T[80 + sl]));

        float4 dq;
        dq.x = w0.x * x0.x; dq.y = w0.y * x0.y;
        dq.z = w0.z * x0.z; dq.w = w0.w * x0.w;

        const float4 mR = make_float4(w1.x * x1.x, w1.y * x1.y, w1.z * x1.z, w1.w * x1.w);
        const float4 mM = make_float4(w2.x * x2.x, w2.y * x2.y, w2.z * x2.z, w2.w * x2.w);

        float4 d0, d1, d2;
        d0.x = fmaf(mR.x, dx, mM.x * m0.x); d0.y = fmaf(mR.y, dx, mM.y * m0.y);
        d0.z = fmaf(mR.z, dx, mM.z * m0.z); d0.w = fmaf(mR.w, dx, mM.w * m0.w);
        d1.x = fmaf(mR.x, dy, mM.x * m1.x); d1.y = fmaf(mR.y, dy, mM.y * m1.y);
        d1.z = fmaf(mR.z, dy, mM.z * m1.z); d1.w = fmaf(mR.w, dy, mM.w * m1.w);
        d2.x = fmaf(mR.x, dz, mM.x * m2.x); d2.y = fmaf(mR.y, dz, mM.y * m2.y);
        d2.z = fmaf(mR.z, dz, mM.z * m2.z); d2.w = fmaf(mR.w, dz, mM.w * m2.w);

        red4(out + (size_t)i * 64 + sl * 4, dq);
        float* om = out + (size_t)NATOMS * 64 + (size_t)i * 192 + sl * 4;
        red4(om,       d0);
        red4(om + 64,  d1);
        red4(om + 128, d2);
    }
}

// ---------------------------------------------------------------------------
// launch
// ---------------------------------------------------------------------------
extern "C" void kernel_launch(void* const* d_in, const int* in_sizes, int n_in,
                              void* d_out, int out_size)
{
    int iq = -1, imu = -1, iW = -1, idir = -1, ii = -1, ij = -1;
    int iW1 = -1, ib1 = -1, iW2 = -1, ib2 = -1;
    for (int k = 0; k < n_in; k++) {
        long s = in_sizes[k];
        if      (s == (long)NATOMS * 64)   iq  = k;
        else if (s == (long)NATOMS * 192)  imu = k;
        else if (s == (long)NEDGES * 192)  iW  = k;
        else if (s == (long)NEDGES * 3)    idir = k;
        else if (s == (long)NEDGES)        { if (ii < 0) ii = k; else ij = k; }
        else if (s == 64 * 64)             iW1 = k;
        else if (s == 64)                  ib1 = k;
        else if (s == 64 * 192)            iW2 = k;
        else if (s == 192)                 ib2 = k;
    }

    const float* q   = (const float*)d_in[iq];
    const float* mu  = (const float*)d_in[imu];
    const float* Wij = (const float*)d_in[iW];
    const float* dir = (const float*)d_in[idir];
    const int*  idxi = (const int*)d_in[ii];
    const int*  idxj = (const int*)d_in[ij];
    const float* W1  = (const float*)d_in[iW1];
    const float* b1  = (const float*)d_in[ib1];
    const float* W2  = (const float*)d_in[iW2];
    const float* b2  = (const float*)d_in[ib2];
    float* out = (float*)d_out;

    // per-atom MLP on tensor cores -> fp16 x part of g_xm
    painn_mlp_tc<<<(NATOMS + 127) / 128, 256>>>(q, W1, b1, W2, b2);

    // out = concat(q, mu) + fp16 mu table
    {
        const int total2 = NATOMS * 128;
        init_fuse_kernel<<<(total2 + 255) / 256, 256>>>(q, mu, out);
    }

    // edge scatter in original order (16 edges per warp)
    {
        const int warps = (NEDGES + 15) / 16;
        const int blocks = (warps * 32 + 255) / 256;
        painn_edge_kernel<<<blocks, 256>>>(Wij, dir, idxi, idxj, out);
    }
}

// round 12
// speedup vs baseline: 1.5434x; 1.1471x over previous
#include <cuda_runtime.h>
#include <cuda_fp16.h>
#include <cstdint>

#define NATOMS 50000
#define NEDGES 800000

// scratch: per atom 96 half2 of x (MLP output), then 96 half2 of mu
__device__ __half2 g_xm[NATOMS * 192];

// ---------------------------------------------------------------------------
// helpers
// ---------------------------------------------------------------------------
__device__ __forceinline__ uint32_t smaddr(const void* p) {
    return (uint32_t)__cvta_generic_to_shared(p);
}
__device__ __forceinline__ uint32_t f2h2(float a, float b) {
    __half2 h = __floats2half2_rn(a, b);
    return *reinterpret_cast<uint32_t*>(&h);
}
__device__ __forceinline__ float silu(float v) {
    return v / (1.0f + __expf(-v));
}

// ---------------------------------------------------------------------------
// Kernel A: per-atom MLP on tensor cores (unchanged from R11 win).
// ---------------------------------------------------------------------------
__global__ __launch_bounds__(256) void painn_mlp_tc(
    const float* __restrict__ q,
    const float* __restrict__ W1, const float* __restrict__ b1,
    const float* __restrict__ W2, const float* __restrict__ b2)
{
    __shared__ __half sH[128 * 64];
    __shared__ __half sW1[64 * 64];
    __shared__ __half sW2[64 * 192];

    const int t = threadIdx.x;
    const int atom0 = blockIdx.x * 128;

    for (int idx = t; idx < 64 * 16; idx += 256) {
        int r = idx >> 4, c4 = idx & 15;
        float4 v = __ldg((const float4*)W1 + r * 16 + c4);
        int blk = (c4 >> 1) ^ (r & 7);
        __half2* d = (__half2*)&sW1[r * 64 + blk * 8 + (c4 & 1) * 4];
        d[0] = __floats2half2_rn(v.x, v.y);
        d[1] = __floats2half2_rn(v.z, v.w);
    }
    for (int idx = t; idx < 64 * 48; idx += 256) {
        int r = idx / 48, c4 = idx % 48;
        float4 v = __ldg((const float4*)W2 + r * 48 + c4);
        int blk = (c4 >> 1) ^ (r & 7);
        __half2* d = (__half2*)&sW2[r * 192 + blk * 8 + (c4 & 1) * 4];
        d[0] = __floats2half2_rn(v.x, v.y);
        d[1] = __floats2half2_rn(v.z, v.w);
    }
    __syncthreads();

    const int w    = t >> 5;
    const int lane = t & 31;
    const int r    = lane >> 2;
    const int cc   = (lane & 3) * 2;

    uint32_t A[4][4];
    {
        const int row0 = atom0 + w * 16 + r;
        const int row1 = row0 + 8;
        const bool v0 = row0 < NATOMS, v1 = row1 < NATOMS;
        const float2* q0 = (const float2*)(q + (size_t)row0 * 64);
        const float2* q1 = (const float2*)(q + (size_t)row1 * 64);
#pragma unroll
        for (int kt = 0; kt < 4; kt++) {
            int k2 = kt * 8 + (cc >> 1);
            float2 f0 = v0 ? __ldg(&q0[k2])     : make_float2(0.f, 0.f);
            float2 f1 = v1 ? __ldg(&q1[k2])     : make_float2(0.f, 0.f);
            float2 f2 = v0 ? __ldg(&q0[k2 + 4]) : make_float2(0.f, 0.f);
            float2 f3 = v1 ? __ldg(&q1[k2 + 4]) : make_float2(0.f, 0.f);
            A[kt][0] = f2h2(f0.x, f0.y);
            A[kt][1] = f2h2(f1.x, f1.y);
            A[kt][2] = f2h2(f2.x, f2.y);
            A[kt][3] = f2h2(f3.x, f3.y);
        }
    }

    const int lrow = lane & 15;
#pragma unroll
    for (int nt = 0; nt < 8; nt++) {
        float c0 = 0.f, c1 = 0.f, c2 = 0.f, c3 = 0.f;
#pragma unroll
        for (int kt = 0; kt < 4; kt++) {
            int row = kt * 16 + lrow;
            int blk = nt ^ (row & 7);
            uint32_t addr = smaddr(&sW1[row * 64 + blk * 8]);
            uint32_t b0, b1r;
            asm volatile("ldmatrix.sync.aligned.m8n8.x2.trans.shared.b16 {%0,%1}, [%2];"
                         : "=r"(b0), "=r"(b1r) : "r"(addr));
            asm volatile("mma.sync.aligned.m16n8k16.row.col.f32.f16.f16.f32 "
                         "{%0,%1,%2,%3}, {%4,%5,%6,%7}, {%8,%9}, {%0,%1,%2,%3};"
                         : "+f"(c0), "+f"(c1), "+f"(c2), "+f"(c3)
                         : "r"(A[kt][0]), "r"(A[kt][1]), "r"(A[kt][2]), "r"(A[kt][3]),
                           "r"(b0), "r"(b1r));
        }
        int col = nt * 8 + cc;
        float bb0 = __ldg(&b1[col]), bb1 = __ldg(&b1[col + 1]);
        int hr0 = w * 16 + r, hr1 = hr0 + 8;
        int blk = nt ^ (r & 7);
        *(__half2*)&sH[hr0 * 64 + blk * 8 + cc] =
            __floats2half2_rn(silu(c0 + bb0), silu(c1 + bb1));
        *(__half2*)&sH[hr1 * 64 + blk * 8 + cc] =
            __floats2half2_rn(silu(c2 + bb0), silu(c3 + bb1));
    }
    __syncwarp();

    uint32_t H[4][4];
#pragma unroll
    for (int kt = 0; kt < 4; kt++) {
        int row = w * 16 + lrow;
        int blk = (kt * 2 + (lane >> 4)) ^ (row & 7);
        uint32_t addr = smaddr(&sH[row * 64 + blk * 8]);
        asm volatile("ldmatrix.sync.aligned.m8n8.x4.shared.b16 {%0,%1,%2,%3}, [%4];"
                     : "=r"(H[kt][0]), "=r"(H[kt][1]), "=r"(H[kt][2]), "=r"(H[kt][3])
                     : "r"(addr));
    }

    const int row0 = atom0 + w * 16 + r;
    const int row1 = row0 + 8;
#pragma unroll
    for (int nt = 0; nt < 24; nt++) {
        float c0 = 0.f, c1 = 0.f, c2 = 0.f, c3 = 0.f;
#pragma unroll
        for (int kt = 0; kt < 4; kt++) {
            int row = kt * 16 + lrow;
            int blk = nt ^ (row & 7);
            uint32_t addr = smaddr(&sW2[row * 192 + blk * 8]);
            uint32_t b0, b1r;
            asm volatile("ldmatrix.sync.aligned.m8n8.x2.trans.shared.b16 {%0,%1}, [%2];"
                         : "=r"(b0), "=r"(b1r) : "r"(addr));
            asm volatile("mma.sync.aligned.m16n8k16.row.col.f32.f16.f16.f32 "
                         "{%0,%1,%2,%3}, {%4,%5,%6,%7}, {%8,%9}, {%0,%1,%2,%3};"
                         : "+f"(c0), "+f"(c1), "+f"(c2), "+f"(c3)
                         : "r"(H[kt][0]), "r"(H[kt][1]), "r"(H[kt][2]), "r"(H[kt][3]),
                           "r"(b0), "r"(b1r));
        }
        int col = nt * 8 + cc;
        float bb0 = __ldg(&b2[col]), bb1 = __ldg(&b2[col + 1]);
        if (row0 < NATOMS)
            g_xm[(size_t)row0 * 192 + (col >> 1)] = __floats2half2_rn(c0 + bb0, c1 + bb1);
        if (row1 < NATOMS)
            g_xm[(size_t)row1 * 192 + (col >> 1)] = __floats2half2_rn(c2 + bb0, c3 + bb1);
    }
}

// ---------------------------------------------------------------------------
// Fused: out = concat(q, mu)  AND  g_xm[:,96:192] = fp16(mu)
// ---------------------------------------------------------------------------
__global__ __launch_bounds__(256) void init_fuse_kernel(
    const float* __restrict__ q, const float* __restrict__ mu,
    float* __restrict__ out)
{
    const int NQ2 = NATOMS * 32;
    const int NT2 = NATOMS * 128;
    int i = blockIdx.x * blockDim.x + threadIdx.x;
    if (i < NQ2) {
        ((float2*)out)[i] = ((const float2*)q)[i];
    } else if (i < NT2) {
        int m = i - NQ2;
        float2 v = __ldg((const float2*)mu + m);
        ((float2*)out)[i] = v;
        g_xm[(size_t)(m / 96) * 192 + 96 + (m % 96)] = __floats2half2_rn(v.x, v.y);
    }
}

// ---------------------------------------------------------------------------
// Kernel C: edges in original order, half-warp per edge.
// Streaming operands (Wij, dir, idx) loaded EVICT-FIRST (__ldcs) so the
// g_xm gather table stays L2-resident. Gathers via __ldg (evict-normal).
// ---------------------------------------------------------------------------
__device__ __forceinline__ void red4(float* p, float4 v) {
    asm volatile("red.global.add.v4.f32 [%0], {%1, %2, %3, %4};"
                 :: "l"(p), "f"(v.x), "f"(v.y), "f"(v.z), "f"(v.w)
                 : "memory");
}

__device__ __forceinline__ float4 h4_to_f4(uint2 u) {
    __half2 lo = *(__half2*)&u.x;
    __half2 hi = *(__half2*)&u.y;
    float2 a = __half22float2(lo);
    float2 b = __half22float2(hi);
    return make_float4(a.x, a.y, b.x, b.y);
}

__global__ __launch_bounds__(256) void painn_edge_kernel(
    const float* __restrict__ Wij, const float* __restrict__ dir_ij,
    const int* __restrict__ idx_i, const int* __restrict__ idx_j,
    float* __restrict__ out)
{
    const int warp = (blockIdx.x * blockDim.x + threadIdx.x) >> 5;
    const int lane = threadIdx.x & 31;
    const int sub = lane >> 4;
    const int sl  = lane & 15;

    const int e0 = warp * 16;
    if (e0 >= NEDGES) return;

#pragma unroll 4
    for (int e = e0 + sub; e < e0 + 16; e += 2) {
        const int i = __ldcs(&idx_i[e]);
        const int j = __ldcs(&idx_j[e]);

        const float dx = __ldcs(&dir_ij[(size_t)e * 3 + 0]);
        const float dy = __ldcs(&dir_ij[(size_t)e * 3 + 1]);
        const float dz = __ldcs(&dir_ij[(size_t)e * 3 + 2]);

        const float4* W4 = (const float4*)(Wij + (size_t)e * 192);
        const uint2* T = (const uint2*)(g_xm + (size_t)j * 192);

        const float4 w0 = __ldcs(&W4[sl]);
        const float4 w1 = __ldcs(&W4[16 + sl]);
        const float4 w2 = __ldcs(&W4[32 + sl]);
        const float4 x0 = h4_to_f4(__ldg(&T[sl]));
        const float4 x1 = h4_to_f4(__ldg(&T[16 + sl]));
        const float4 x2 = h4_to_f4(__ldg(&T[32 + sl]));
        const float4 m0 = h4_to_f4(__ldg(&T[48 + sl]));
        const float4 m1 = h4_to_f4(__ldg(&T[64 + sl]));
        const float4 m2 = h4_to_f4(__ldg(&T[80 + sl]));

        float4 dq;
        dq.x = w0.x * x0.x; dq.y = w0.y * x0.y;
        dq.z = w0.z * x0.z; dq.w = w0.w * x0.w;

        const float4 mR = make_float4(w1.x * x1.x, w1.y * x1.y, w1.z * x1.z, w1.w * x1.w);
        const float4 mM = make_float4(w2.x * x2.x, w2.y * x2.y, w2.z * x2.z, w2.w * x2.w);

        float4 d0, d1, d2;
        d0.x = fmaf(mR.x, dx, mM.x * m0.x); d0.y = fmaf(mR.y, dx, mM.y * m0.y);
        d0.z = fmaf(mR.z, dx, mM.z * m0.z); d0.w = fmaf(mR.w, dx, mM.w * m0.w);
        d1.x = fmaf(mR.x, dy, mM.x * m1.x); d1.y = fmaf(mR.y, dy, mM.y * m1.y);
        d1.z = fmaf(mR.z, dy, mM.z * m1.z); d1.w = fmaf(mR.w, dy, mM.w * m1.w);
        d2.x = fmaf(mR.x, dz, mM.x * m2.x); d2.y = fmaf(mR.y, dz, mM.y * m2.y);
        d2.z = fmaf(mR.z, dz, mM.z * m2.z); d2.w = fmaf(mR.w, dz, mM.w * m2.w);

        red4(out + (size_t)i * 64 + sl * 4, dq);
        float* om = out + (size_t)NATOMS * 64 + (size_t)i * 192 + sl * 4;
        red4(om,       d0);
        red4(om + 64,  d1);
        red4(om + 128, d2);
    }
}

// ---------------------------------------------------------------------------
// launch
// ---------------------------------------------------------------------------
extern "C" void kernel_launch(void* const* d_in, const int* in_sizes, int n_in,
                              void* d_out, int out_size)
{
    int iq = -1, imu = -1, iW = -1, idir = -1, ii = -1, ij = -1;
    int iW1 = -1, ib1 = -1, iW2 = -1, ib2 = -1;
    for (int k = 0; k < n_in; k++) {
        long s = in_sizes[k];
        if      (s == (long)NATOMS * 64)   iq  = k;
        else if (s == (long)NATOMS * 192)  imu = k;
        else if (s == (long)NEDGES * 192)  iW  = k;
        else if (s == (long)NEDGES * 3)    idir = k;
        else if (s == (long)NEDGES)        { if (ii < 0) ii = k; else ij = k; }
        else if (s == 64 * 64)             iW1 = k;
        else if (s == 64)                  ib1 = k;
        else if (s == 64 * 192)            iW2 = k;
        else if (s == 192)                 ib2 = k;
    }

    const float* q   = (const float*)d_in[iq];
    const float* mu  = (const float*)d_in[imu];
    const float* Wij = (const float*)d_in[iW];
    const float* dir = (const float*)d_in[idir];
    const int*  idxi = (const int*)d_in[ii];
    const int*  idxj = (const int*)d_in[ij];
    const float* W1  = (const float*)d_in[iW1];
    const float* b1  = (const float*)d_in[ib1];
    const float* W2  = (const float*)d_in[iW2];
    const float* b2  = (const float*)d_in[ib2];
    float* out = (float*)d_out;

    // per-atom MLP on tensor cores -> fp16 x part of g_xm
    painn_mlp_tc<<<(NATOMS + 127) / 128, 256>>>(q, W1, b1, W2, b2);

    // out = concat(q, mu) + fp16 mu table
    {
        const int total2 = NATOMS * 128;
        init_fuse_kernel<<<(total2 + 255) / 256, 256>>>(q, mu, out);
    }

    // edge scatter in original order (16 edges per warp)
    {
        const int warps = (NEDGES + 15) / 16;
        const int blocks = (warps * 32 + 255) / 256;
        painn_edge_kernel<<<blocks, 256>>>(Wij, dir, idxi, idxj, out);
    }
}